// round 16
// baseline (speedup 1.0000x reference)
#include <cuda_runtime.h>
#include <cuda_fp16.h>
#include <math.h>
#include <stdint.h>

// Problem constants (fixed by the reference)
#define Hdim 1024
#define Idim 2048
#define Edim 8
#define Ntok 8192            // B*T
#define KSEL 2
#define NSLOT (Ntok * KSEL)  // 16384
#define W1ELEMS (Edim * Idim * Hdim)
#define W2ELEMS (Edim * Hdim * Idim)

// ---------------- device scratch ---------------------------------------------
// g_counts is zero-initialized at module load; combine_kernel re-zeroes it at
// the end of every launch, so each graph replay starts from counts == 0.
__device__ __half g_xtok[(size_t)Ntok * Hdim];   // fp16 x, TOKEN order
__device__ __half g_hidh[(size_t)NSLOT * Idim];  // fc1 out after silu (fp16, pos order)
__device__ __half g_ogh [(size_t)NSLOT * Hdim];  // fc2 out (fp16, pos order)
__device__ __half g_w1h [W1ELEMS];
__device__ __half g_w2h [W2ELEMS];
__device__ int    g_counts[Edim];
__device__ int    g_off[Edim];
__device__ int    g_expert[NSLOT];
__device__ int    g_rank[NSLOT];
__device__ float  g_w[NSLOT];
__device__ int    g_pos[NSLOT];
__device__ int    g_inv[NSLOT];     // pos -> token
__device__ int    g_tiles1[2048];   // packed e<<13 | mb<<5 | nb
__device__ int    g_tiles2[2048];
__device__ int    g_nt[2];

// ---------------- helpers -----------------------------------------------------
__device__ __forceinline__ uint32_t smem_u32(const void* p) {
    uint32_t a;
    asm("{ .reg .u64 t; cvta.to.shared.u64 t, %1; cvt.u32.u64 %0, t; }" : "=r"(a) : "l"(p));
    return a;
}

__device__ __forceinline__ void cp16(uint32_t dst, const void* src) {
    asm volatile("cp.async.cg.shared.global [%0], [%1], 16;" :: "r"(dst), "l"(src));
}

__device__ __forceinline__ void ldsm_x4(uint32_t addr, uint32_t& r0, uint32_t& r1,
                                        uint32_t& r2, uint32_t& r3) {
    asm volatile("ldmatrix.sync.aligned.m8n8.x4.shared.b16 {%0,%1,%2,%3}, [%4];"
                 : "=r"(r0), "=r"(r1), "=r"(r2), "=r"(r3) : "r"(addr));
}

__device__ __forceinline__ void mma_f16(float* d, const uint32_t* a, uint32_t b0, uint32_t b1) {
    asm volatile(
        "mma.sync.aligned.m16n8k16.row.col.f32.f16.f16.f32 "
        "{%0,%1,%2,%3}, {%4,%5,%6,%7}, {%8,%9}, {%0,%1,%2,%3};"
        : "+f"(d[0]), "+f"(d[1]), "+f"(d[2]), "+f"(d[3])
        : "r"(a[0]), "r"(a[1]), "r"(a[2]), "r"(a[3]), "r"(b0), "r"(b1));
}

// ---------------- ancillary kernels ------------------------------------------

// gate: x row staged to SMEM once; 8 warps dot from SMEM (L1 traffic /8)
__global__ __launch_bounds__(256) void gate_kernel(const float* __restrict__ x,
                                                   const float* __restrict__ Wg) {
    __shared__ float xs[Hdim];
    __shared__ float logits[Edim];
    int n    = blockIdx.x;
    int warp = threadIdx.x >> 5;
    int lane = threadIdx.x & 31;

    ((float4*)xs)[threadIdx.x] = ((const float4*)(x + (size_t)n * Hdim))[threadIdx.x];
    __syncthreads();

    const float4* xs4 = (const float4*)xs;
    const float4* wr4 = (const float4*)(Wg + (size_t)warp * Hdim);
    float s = 0.f;
    #pragma unroll
    for (int i = 0; i < 8; i++) {
        float4 a = xs4[lane + 32 * i];
        float4 b = wr4[lane + 32 * i];
        s += a.x * b.x + a.y * b.y + a.z * b.z + a.w * b.w;
    }
    #pragma unroll
    for (int o = 16; o; o >>= 1) s += __shfl_xor_sync(0xFFFFFFFFu, s, o);

    if (lane == 0) logits[warp] = s;
    __syncthreads();

    if (threadIdx.x == 0) {
        float m = logits[0];
        #pragma unroll
        for (int e = 1; e < Edim; e++) m = fmaxf(m, logits[e]);
        float p[Edim]; float den = 0.f;
        #pragma unroll
        for (int e = 0; e < Edim; e++) { p[e] = expf(logits[e] - m); den += p[e]; }
        int i0 = 0;
        #pragma unroll
        for (int e = 1; e < Edim; e++) if (p[e] > p[i0]) i0 = e;
        int i1 = (i0 == 0) ? 1 : 0;
        #pragma unroll
        for (int e = 0; e < Edim; e++) if (e != i0 && p[e] > p[i1]) i1 = e;
        float inv = 1.f / den;
        int r0 = atomicAdd(&g_counts[i0], 1);
        int r1 = atomicAdd(&g_counts[i1], 1);
        g_expert[2*n]   = i0; g_rank[2*n]   = r0; g_w[2*n]   = p[i0] * inv;
        g_expert[2*n+1] = i1; g_rank[2*n+1] = r1; g_w[2*n+1] = p[i1] * inv;
    }
}

// x f32 -> f16, token order (independent of gating; runs on fork stream)
__global__ __launch_bounds__(256) void xconv_kernel(const float* __restrict__ x,
                                                    __half* __restrict__ xtok) {
    int i = blockIdx.x * blockDim.x + threadIdx.x;   // over Ntok*Hdim/8
    float4 v0 = ((const float4*)x)[2*i];
    float4 v1 = ((const float4*)x)[2*i+1];
    __half2 h[4];
    h[0] = __floats2half2_rn(v0.x, v0.y);
    h[1] = __floats2half2_rn(v0.z, v0.w);
    h[2] = __floats2half2_rn(v1.x, v1.y);
    h[3] = __floats2half2_rn(v1.z, v1.w);
    ((uint4*)xtok)[i] = *(uint4*)h;
}

// prefix-scan + build exact tile worklists for both grouped GEMMs
__global__ __launch_bounds__(256) void scan_build_kernel() {
    __shared__ int pm[Edim + 1];
    if (threadIdx.x == 0) {
        int a = 0, g = 0;
        pm[0] = 0;
        #pragma unroll
        for (int e = 0; e < Edim; e++) {
            g_off[e] = a; a += g_counts[e];
            g += (g_counts[e] + 127) >> 7;
            pm[e + 1] = g;
        }
        g_nt[0] = pm[Edim] * 8;
        g_nt[1] = pm[Edim] * 4;
    }
    __syncthreads();
    int total_mb = pm[Edim];
    for (int i = threadIdx.x; i < total_mb * 8; i += 256) {
        int gmb = i >> 3, nb = i & 7;
        int e = 0;
        #pragma unroll
        for (int k = 0; k < Edim; k++) if (gmb >= pm[k + 1]) e = k + 1;
        g_tiles1[i] = (e << 13) | ((gmb - pm[e]) << 5) | nb;
    }
    for (int i = threadIdx.x; i < total_mb * 4; i += 256) {
        int gmb = i >> 2, nb = i & 3;
        int e = 0;
        #pragma unroll
        for (int k = 0; k < Edim; k++) if (gmb >= pm[k + 1]) e = k + 1;
        g_tiles2[i] = (e << 13) | ((gmb - pm[e]) << 5) | nb;
    }
}

// tiny: pos + inverse permutation
__global__ __launch_bounds__(256) void pos_kernel() {
    int slot = blockIdx.x * blockDim.x + threadIdx.x;
    if (slot >= NSLOT) return;
    int e   = g_expert[slot];
    int pos = g_off[e] + g_rank[slot];
    g_pos[slot] = pos;
    g_inv[pos]  = slot >> 1;
}

// float -> half weight conversion, 8 elems per thread
__global__ __launch_bounds__(256) void f2h_kernel(const float* __restrict__ s,
                                                  __half* __restrict__ d, int n8) {
    int i = blockIdx.x * blockDim.x + threadIdx.x;
    if (i >= n8) return;
    float4 v0 = ((const float4*)s)[2*i];
    float4 v1 = ((const float4*)s)[2*i+1];
    __half2 h[4];
    h[0] = __floats2half2_rn(v0.x, v0.y);
    h[1] = __floats2half2_rn(v0.z, v0.w);
    h[2] = __floats2half2_rn(v1.x, v1.y);
    h[3] = __floats2half2_rn(v1.z, v1.w);
    ((uint4*)d)[i] = *(uint4*)h;
}

// combine (8 cols/thread, uint4 loads) + end-of-launch re-zero of g_counts
__global__ __launch_bounds__(256) void combine_kernel(float* __restrict__ out) {
    int idx = blockIdx.x * blockDim.x + threadIdx.x;   // over N*H/8
    if (blockIdx.x == 0 && threadIdx.x < Edim) g_counts[threadIdx.x] = 0;
    int n = idx >> 7;            // Hdim/8 = 128 chunks per token
    int c = idx & 127;
    float w0 = g_w[2*n],   w1 = g_w[2*n+1];
    int   p0 = g_pos[2*n], p1 = g_pos[2*n+1];
    uint4 av = ((const uint4*)(g_ogh + (size_t)p0 * Hdim))[c];
    uint4 bv = ((const uint4*)(g_ogh + (size_t)p1 * Hdim))[c];
    const __half2* ah = (const __half2*)&av;
    const __half2* bh = (const __half2*)&bv;
    float4 r0, r1;
    {
        float2 fa = __half22float2(ah[0]), fb = __half22float2(bh[0]);
        r0.x = w0 * fa.x + w1 * fb.x;  r0.y = w0 * fa.y + w1 * fb.y;
        fa = __half22float2(ah[1]); fb = __half22float2(bh[1]);
        r0.z = w0 * fa.x + w1 * fb.x;  r0.w = w0 * fa.y + w1 * fb.y;
        fa = __half22float2(ah[2]); fb = __half22float2(bh[2]);
        r1.x = w0 * fa.x + w1 * fb.x;  r1.y = w0 * fa.y + w1 * fb.y;
        fa = __half22float2(ah[3]); fb = __half22float2(bh[3]);
        r1.z = w0 * fa.x + w1 * fb.x;  r1.w = w0 * fa.y + w1 * fb.y;
    }
    ((float4*)out)[2*idx]   = r0;
    ((float4*)out)[2*idx+1] = r1;
}

// ---------------- persistent fp16 mma.sync grouped GEMM ----------------------
// CTA tile 128x256x64; 8 warps 2(m)x4(n), warp tile 64x64 (4x8 m16n8k16).
// 4-stage cp.async pipeline (wait_group 2 = depth-2 prefetch, proven).
// Intra-iteration fragment double-buffer: ks+1 LDSMs before ks MMAs.
// MODE 1: A via g_inv (token-order x), silu epilogue -> half C.
// MODE 0: A direct (pos order), plain half epilogue -> half C.
#define STAGE_BYTES 49152
#define NSTAGE 4
#define SMEM_TOTAL (NSTAGE * STAGE_BYTES)

template <int MODE>
__global__ __launch_bounds__(256, 1) void moe_gemm_f16(
    const __half* __restrict__ Ab, const __half* __restrict__ Wb,
    __half* __restrict__ Cb, int Kdim, int Ncols,
    const int* __restrict__ tiles, int nt_idx)
{
    int NT = g_nt[nt_idx];
    int li = blockIdx.x;
    if (li >= NT) return;

    extern __shared__ char smem[];
    uint32_t sb = smem_u32(smem);
    int tid = threadIdx.x, wid = tid >> 5, lane = tid & 31;

    uint32_t d1 = sb + (uint32_t)tid * 128u;
    uint32_t x1 = (uint32_t)(tid & 7);
    uint32_t d2 = sb + (uint32_t)(tid + 256) * 128u;
    uint32_t x2 = (uint32_t)((tid + 256) & 7);
    bool two = tid < 128;

    int mw = wid & 1, nw = wid >> 1;
    int mA0 = mw * 64, nB0 = nw * 64;
    int rA = mA0 + ((lane >> 3) & 1) * 8 + (lane & 7);
    uint32_t jhA = (uint32_t)(lane >> 4);
    uint32_t xA  = (uint32_t)(rA & 7);
    uint32_t baseA[4];
    #pragma unroll
    for (int mt = 0; mt < 4; mt++) baseA[mt] = sb + (uint32_t)(rA + mt * 16) * 128u;
    uint32_t jhB = (uint32_t)((lane >> 3) & 1);
    uint32_t baseB[4], xB[4];
    #pragma unroll
    for (int p = 0; p < 4; p++) {
        int rB = nB0 + p * 16 + (lane >> 4) * 8 + (lane & 7);
        baseB[p] = sb + 16384u + (uint32_t)rB * 128u;
        xB[p]    = (uint32_t)(rB & 7);
    }

    int niter = Kdim >> 6;   // 16 or 32; % 4 == 0

    int t  = tiles[li];
    int e  = t >> 13, mb = (t >> 5) & 0xFF, nb = t & 31;
    int Me = g_counts[e], off = g_off[e];
    int m0 = mb * 128,  n0 = nb * 256;
    const __half* gs1;
    if (tid < 128) {
        int ridx = off + min(m0 + tid, NSLOT - 1 - off);
        gs1 = (MODE == 1) ? (Ab + (size_t)g_inv[ridx] * Kdim)
                          : (Ab + (size_t)ridx * Kdim);
    } else {
        gs1 = Wb + (size_t)e * Ncols * Kdim + (size_t)(n0 + tid - 128) * Kdim;
    }
    const __half* gs2 = Wb + (size_t)e * Ncols * Kdim + (size_t)(n0 + (tid & 127) + 128) * Kdim;

    #pragma unroll
    for (int s = 0; s < NSTAGE - 1; s++) {
        uint32_t so = (uint32_t)s * STAGE_BYTES;
        const __half* g1 = gs1 + s * 64;
        #pragma unroll
        for (int j = 0; j < 8; j++) cp16(d1 + so + (((uint32_t)j ^ x1) << 4), g1 + j * 8);
        if (two) {
            const __half* g2 = gs2 + s * 64;
            #pragma unroll
            for (int j = 0; j < 8; j++) cp16(d2 + so + (((uint32_t)j ^ x2) << 4), g2 + j * 8);
        }
        asm volatile("cp.async.commit_group;");
    }

    float acc[4][8][4];
    uint32_t afr[2][16], bfr[2][16];

    while (true) {
        #pragma unroll
        for (int i = 0; i < 4; i++)
            #pragma unroll
            for (int j = 0; j < 8; j++)
                #pragma unroll
                for (int q = 0; q < 4; q++) acc[i][j][q] = 0.f;

        int li_n = li + gridDim.x;
        bool hn = li_n < NT;
        int Men = 0, offn = 0, m0n = 0, n0n = 0;
        const __half *gs1n = nullptr, *gs2n = nullptr;
        if (hn) {
            int tn = tiles[li_n];
            int en = tn >> 13, mbn = (tn >> 5) & 0xFF, nbn = tn & 31;
            Men = g_counts[en]; offn = g_off[en];
            m0n = mbn * 128; n0n = nbn * 256;
            if (tid < 128) {
                int ridx = offn + min(m0n + tid, NSLOT - 1 - offn);
                gs1n = (MODE == 1) ? (Ab + (size_t)g_inv[ridx] * Kdim)
                                   : (Ab + (size_t)ridx * Kdim);
            } else {
                gs1n = Wb + (size_t)en * Ncols * Kdim + (size_t)(n0n + tid - 128) * Kdim;
            }
            gs2n = Wb + (size_t)en * Ncols * Kdim + (size_t)(n0n + (tid & 127) + 128) * Kdim;
        }

        for (int it = 0; it < niter; ++it) {
            asm volatile("cp.async.wait_group 2;");
            __syncthreads();

            uint32_t soff = (uint32_t)(it & (NSTAGE - 1)) * STAGE_BYTES;

            // load ks = 0 into buf 0
            #pragma unroll
            for (int mt = 0; mt < 4; mt++) {
                uint32_t ad = baseA[mt] + soff + (((0u + jhA) ^ xA) << 4);
                ldsm_x4(ad, afr[0][4*mt+0], afr[0][4*mt+1], afr[0][4*mt+2], afr[0][4*mt+3]);
            }
            #pragma unroll
            for (int p = 0; p < 4; p++) {
                uint32_t bd = baseB[p] + soff + (((0u + jhB) ^ xB[p]) << 4);
                ldsm_x4(bd, bfr[0][4*p+0], bfr[0][4*p+1], bfr[0][4*p+2], bfr[0][4*p+3]);
            }

            #pragma unroll
            for (int ks = 0; ks < 4; ks++) {
                int cur = ks & 1, nxt = cur ^ 1;
                if (ks < 3) {   // prefetch ks+1 fragments before ks MMAs
                    uint32_t ko = (uint32_t)((ks + 1) << 1);
                    #pragma unroll
                    for (int mt = 0; mt < 4; mt++) {
                        uint32_t ad = baseA[mt] + soff + (((ko + jhA) ^ xA) << 4);
                        ldsm_x4(ad, afr[nxt][4*mt+0], afr[nxt][4*mt+1],
                                    afr[nxt][4*mt+2], afr[nxt][4*mt+3]);
                    }
                    #pragma unroll
                    for (int p = 0; p < 4; p++) {
                        uint32_t bd = baseB[p] + soff + (((ko + jhB) ^ xB[p]) << 4);
                        ldsm_x4(bd, bfr[nxt][4*p+0], bfr[nxt][4*p+1],
                                    bfr[nxt][4*p+2], bfr[nxt][4*p+3]);
                    }
                }
                #pragma unroll
                for (int p = 0; p < 4; p++) {
                    #pragma unroll
                    for (int mt = 0; mt < 4; mt++) {
                        mma_f16(acc[mt][2*p+0], &afr[cur][4*mt], bfr[cur][4*p+0], bfr[cur][4*p+1]);
                        mma_f16(acc[mt][2*p+1], &afr[cur][4*mt], bfr[cur][4*p+2], bfr[cur][4*p+3]);
                    }
                }
            }

            int nx = it + NSTAGE - 1;
            uint32_t so = (uint32_t)(nx & (NSTAGE - 1)) * STAGE_BYTES;
            if (nx < niter) {
                const __half* g1 = gs1 + nx * 64;
                #pragma unroll
                for (int j = 0; j < 8; j++) cp16(d1 + so + (((uint32_t)j ^ x1) << 4), g1 + j * 8);
                if (two) {
                    const __half* g2 = gs2 + nx * 64;
                    #pragma unroll
                    for (int j = 0; j < 8; j++) cp16(d2 + so + (((uint32_t)j ^ x2) << 4), g2 + j * 8);
                }
            } else if (hn) {
                int j0 = nx - niter;   // 0..2
                const __half* g1 = gs1n + j0 * 64;
                #pragma unroll
                for (int j = 0; j < 8; j++) cp16(d1 + so + (((uint32_t)j ^ x1) << 4), g1 + j * 8);
                if (two) {
                    const __half* g2 = gs2n + j0 * 64;
                    #pragma unroll
                    for (int j = 0; j < 8; j++) cp16(d2 + so + (((uint32_t)j ^ x2) << 4), g2 + j * 8);
                }
            }
            asm volatile("cp.async.commit_group;");
        }

        {
            __half* C = Cb + (size_t)off * Ncols;
            #pragma unroll
            for (int mt = 0; mt < 4; mt++) {
                int ml0 = mA0 + mt * 16 + (lane >> 2);
                int ml1 = ml0 + 8;
                bool w0 = (m0 + ml0) < Me;
                bool w1 = (m0 + ml1) < Me;
                __half* c0 = C + (size_t)(m0 + ml0) * Ncols + n0;
                __half* c1 = C + (size_t)(m0 + ml1) * Ncols + n0;
                #pragma unroll
                for (int nt = 0; nt < 8; nt++) {
                    int col = nB0 + nt * 8 + (lane & 3) * 2;
                    float v0 = acc[mt][nt][0], v1 = acc[mt][nt][1];
                    float v2 = acc[mt][nt][2], v3 = acc[mt][nt][3];
                    if (MODE == 1) {
                        v0 = v0 / (1.f + __expf(-v0));
                        v1 = v1 / (1.f + __expf(-v1));
                        v2 = v2 / (1.f + __expf(-v2));
                        v3 = v3 / (1.f + __expf(-v3));
                    }
                    if (w0) *(__half2*)(c0 + col) = __floats2half2_rn(v0, v1);
                    if (w1) *(__half2*)(c1 + col) = __floats2half2_rn(v2, v3);
                }
            }
        }

        if (!hn) break;
        li = li_n; Me = Men; off = offn; m0 = m0n; n0 = n0n;
        gs1 = gs1n; gs2 = gs2n;
    }
}

// ---------------- launch ------------------------------------------------------
extern "C" void kernel_launch(void* const* d_in, const int* in_sizes, int n_in,
                              void* d_out, int out_size) {
    const float* x  = (const float*)d_in[0];
    const float* Wg = (const float*)d_in[1];
    const float* W1 = (const float*)d_in[2];
    const float* W2 = (const float*)d_in[3];
    float* out = (float*)d_out;

    __half *xtok = nullptr, *hidh = nullptr, *ogh = nullptr, *w1h = nullptr, *w2h = nullptr;
    int *tiles1 = nullptr, *tiles2 = nullptr;
    cudaGetSymbolAddress((void**)&xtok,   g_xtok);
    cudaGetSymbolAddress((void**)&hidh,   g_hidh);
    cudaGetSymbolAddress((void**)&ogh,    g_ogh);
    cudaGetSymbolAddress((void**)&w1h,    g_w1h);
    cudaGetSymbolAddress((void**)&w2h,    g_w2h);
    cudaGetSymbolAddress((void**)&tiles1, g_tiles1);
    cudaGetSymbolAddress((void**)&tiles2, g_tiles2);

    static int nsm = 0;
    static cudaStream_t s2;
    static cudaEvent_t ev_fork, ev_w1, ev_w2;
    if (nsm == 0) {
        cudaFuncSetAttribute(moe_gemm_f16<0>, cudaFuncAttributeMaxDynamicSharedMemorySize,
                             SMEM_TOTAL);
        cudaFuncSetAttribute(moe_gemm_f16<1>, cudaFuncAttributeMaxDynamicSharedMemorySize,
                             SMEM_TOTAL);
        cudaDeviceGetAttribute(&nsm, cudaDevAttrMultiProcessorCount, 0);
        if (nsm <= 0) nsm = 148;
        cudaStreamCreateWithFlags(&s2, cudaStreamNonBlocking);
        cudaEventCreateWithFlags(&ev_fork, cudaEventDisableTiming);
        cudaEventCreateWithFlags(&ev_w1,   cudaEventDisableTiming);
        cudaEventCreateWithFlags(&ev_w2,   cudaEventDisableTiming);
    }

    // fork: x conversion + weight conversion overlap gating
    cudaEventRecord(ev_fork, 0);
    cudaStreamWaitEvent(s2, ev_fork, 0);
    xconv_kernel<<<(Ntok * Hdim / 8) / 256, 256, 0, s2>>>(x, xtok);
    f2h_kernel<<<(W1ELEMS / 8 + 255) / 256, 256, 0, s2>>>(W1, w1h, W1ELEMS / 8);
    cudaEventRecord(ev_w1, s2);
    f2h_kernel<<<(W2ELEMS / 8 + 255) / 256, 256, 0, s2>>>(W2, w2h, W2ELEMS / 8);
    cudaEventRecord(ev_w2, s2);

    // main: gate (counts start at 0 — zeroed by combine at end of prior replay,
    // and by static zero-init on the very first run)
    gate_kernel<<<Ntok, 256>>>(x, Wg);
    scan_build_kernel<<<1, 256>>>();
    pos_kernel<<<NSLOT / 256, 256>>>();

    cudaStreamWaitEvent(0, ev_w1, 0);
    // GEMM1: hid = silu(x[g_inv] @ W1[e]^T)   K=H=1024, Ncols=I=2048
    moe_gemm_f16<1><<<nsm, 256, SMEM_TOTAL>>>(xtok, w1h, hidh, Hdim, Idim, tiles1, 0);
    cudaStreamWaitEvent(0, ev_w2, 0);
    // GEMM2: og = hidh @ W2[e]^T              K=I=2048, Ncols=H=1024
    moe_gemm_f16<0><<<nsm, 256, SMEM_TOTAL>>>(hidh, w2h, ogh, Idim, Hdim, tiles2, 1);

    combine_kernel<<<(Ntok * Hdim / 8) / 256, 256>>>(out);
}

// round 17
// speedup vs baseline: 1.0153x; 1.0153x over previous
#include <cuda_runtime.h>
#include <cuda_fp16.h>
#include <math.h>
#include <stdint.h>

// Problem constants (fixed by the reference)
#define Hdim 1024
#define Idim 2048
#define Edim 8
#define Ntok 8192            // B*T
#define KSEL 2
#define NSLOT (Ntok * KSEL)  // 16384
#define W1ELEMS (Edim * Idim * Hdim)
#define W2ELEMS (Edim * Hdim * Idim)

// ---------------- device scratch ---------------------------------------------
// g_counts / g_flag are zero-initialized at module load; combine_kernel
// re-zeroes them at the end of every launch (replay invariant).
__device__ __half g_xtok[(size_t)Ntok * Hdim];   // fp16 x, TOKEN order
__device__ __half g_hidh[(size_t)NSLOT * Idim];  // fc1 out after silu (fp16, pos order)
__device__ __half g_ogh [(size_t)NSLOT * Hdim];  // fc2 out (fp16, pos order)
__device__ __half g_w1h [W1ELEMS];
__device__ __half g_w2h [W2ELEMS];
__device__ int    g_counts[Edim];
__device__ int    g_off[Edim];
__device__ int    g_expert[NSLOT];
__device__ int    g_rank[NSLOT];
__device__ float  g_w[NSLOT];
__device__ int    g_pos[NSLOT];
__device__ int    g_inv[NSLOT];     // pos -> token
__device__ int    g_tiles1[2048];   // packed e<<13 | mb<<5 | nb
__device__ int    g_tiles2[2048];
__device__ int    g_nt[2];
__device__ int    g_flag[256];      // per-global-m-block GEMM1 completion count

// ---------------- helpers -----------------------------------------------------
__device__ __forceinline__ uint32_t smem_u32(const void* p) {
    uint32_t a;
    asm("{ .reg .u64 t; cvta.to.shared.u64 t, %1; cvt.u32.u64 %0, t; }" : "=r"(a) : "l"(p));
    return a;
}

__device__ __forceinline__ void cp16(uint32_t dst, const void* src) {
    asm volatile("cp.async.cg.shared.global [%0], [%1], 16;" :: "r"(dst), "l"(src));
}

__device__ __forceinline__ void ldsm_x4(uint32_t addr, uint32_t& r0, uint32_t& r1,
                                        uint32_t& r2, uint32_t& r3) {
    asm volatile("ldmatrix.sync.aligned.m8n8.x4.shared.b16 {%0,%1,%2,%3}, [%4];"
                 : "=r"(r0), "=r"(r1), "=r"(r2), "=r"(r3) : "r"(addr));
}

__device__ __forceinline__ void mma_f16(float* d, const uint32_t* a, uint32_t b0, uint32_t b1) {
    asm volatile(
        "mma.sync.aligned.m16n8k16.row.col.f32.f16.f16.f32 "
        "{%0,%1,%2,%3}, {%4,%5,%6,%7}, {%8,%9}, {%0,%1,%2,%3};"
        : "+f"(d[0]), "+f"(d[1]), "+f"(d[2]), "+f"(d[3])
        : "r"(a[0]), "r"(a[1]), "r"(a[2]), "r"(a[3]), "r"(b0), "r"(b1));
}

// ---------------- ancillary kernels ------------------------------------------

// gate: logits + softmax top-2 + atomic rank assignment (R14-proven)
__global__ __launch_bounds__(256) void gate_kernel(const float* __restrict__ x,
                                                   const float* __restrict__ Wg) {
    int n    = blockIdx.x;
    int warp = threadIdx.x >> 5;
    int lane = threadIdx.x & 31;

    const float* xr = x  + (size_t)n * Hdim;
    const float* wr = Wg + (size_t)warp * Hdim;
    float s = 0.f;
    #pragma unroll 8
    for (int h = lane; h < Hdim; h += 32) s += xr[h] * wr[h];
    #pragma unroll
    for (int o = 16; o; o >>= 1) s += __shfl_xor_sync(0xFFFFFFFFu, s, o);

    __shared__ float logits[Edim];
    if (lane == 0) logits[warp] = s;
    __syncthreads();

    if (threadIdx.x == 0) {
        float m = logits[0];
        #pragma unroll
        for (int e = 1; e < Edim; e++) m = fmaxf(m, logits[e]);
        float p[Edim]; float den = 0.f;
        #pragma unroll
        for (int e = 0; e < Edim; e++) { p[e] = expf(logits[e] - m); den += p[e]; }
        int i0 = 0;
        #pragma unroll
        for (int e = 1; e < Edim; e++) if (p[e] > p[i0]) i0 = e;
        int i1 = (i0 == 0) ? 1 : 0;
        #pragma unroll
        for (int e = 0; e < Edim; e++) if (e != i0 && p[e] > p[i1]) i1 = e;
        float inv = 1.f / den;
        int r0 = atomicAdd(&g_counts[i0], 1);
        int r1 = atomicAdd(&g_counts[i1], 1);
        g_expert[2*n]   = i0; g_rank[2*n]   = r0; g_w[2*n]   = p[i0] * inv;
        g_expert[2*n+1] = i1; g_rank[2*n+1] = r1; g_w[2*n+1] = p[i1] * inv;
    }
}

// x f32 -> f16, token order (independent of gating; runs on fork stream)
__global__ __launch_bounds__(256) void xconv_kernel(const float* __restrict__ x,
                                                    __half* __restrict__ xtok) {
    int i = blockIdx.x * blockDim.x + threadIdx.x;   // over Ntok*Hdim/8
    float4 v0 = ((const float4*)x)[2*i];
    float4 v1 = ((const float4*)x)[2*i+1];
    __half2 h[4];
    h[0] = __floats2half2_rn(v0.x, v0.y);
    h[1] = __floats2half2_rn(v0.z, v0.w);
    h[2] = __floats2half2_rn(v1.x, v1.y);
    h[3] = __floats2half2_rn(v1.z, v1.w);
    ((uint4*)xtok)[i] = *(uint4*)h;
}

// prefix-scan + build exact tile worklists for both grouped GEMMs
__global__ __launch_bounds__(256) void scan_build_kernel() {
    __shared__ int pm[Edim + 1];
    if (threadIdx.x == 0) {
        int a = 0, g = 0;
        pm[0] = 0;
        #pragma unroll
        for (int e = 0; e < Edim; e++) {
            g_off[e] = a; a += g_counts[e];
            g += (g_counts[e] + 127) >> 7;
            pm[e + 1] = g;
        }
        g_nt[0] = pm[Edim] * 8;
        g_nt[1] = pm[Edim] * 4;
    }
    __syncthreads();
    int total_mb = pm[Edim];
    for (int i = threadIdx.x; i < total_mb * 8; i += 256) {
        int gmb = i >> 3, nb = i & 7;
        int e = 0;
        #pragma unroll
        for (int k = 0; k < Edim; k++) if (gmb >= pm[k + 1]) e = k + 1;
        g_tiles1[i] = (e << 13) | ((gmb - pm[e]) << 5) | nb;
    }
    for (int i = threadIdx.x; i < total_mb * 4; i += 256) {
        int gmb = i >> 2, nb = i & 3;
        int e = 0;
        #pragma unroll
        for (int k = 0; k < Edim; k++) if (gmb >= pm[k + 1]) e = k + 1;
        g_tiles2[i] = (e << 13) | ((gmb - pm[e]) << 5) | nb;
    }
}

// tiny: pos + inverse permutation
__global__ __launch_bounds__(256) void pos_kernel() {
    int slot = blockIdx.x * blockDim.x + threadIdx.x;
    if (slot >= NSLOT) return;
    int e   = g_expert[slot];
    int pos = g_off[e] + g_rank[slot];
    g_pos[slot] = pos;
    g_inv[pos]  = slot >> 1;
}

// float -> half weight conversion, 8 elems per thread
__global__ __launch_bounds__(256) void f2h_kernel(const float* __restrict__ s,
                                                  __half* __restrict__ d, int n8) {
    int i = blockIdx.x * blockDim.x + threadIdx.x;
    if (i >= n8) return;
    float4 v0 = ((const float4*)s)[2*i];
    float4 v1 = ((const float4*)s)[2*i+1];
    __half2 h[4];
    h[0] = __floats2half2_rn(v0.x, v0.y);
    h[1] = __floats2half2_rn(v0.z, v0.w);
    h[2] = __floats2half2_rn(v1.x, v1.y);
    h[3] = __floats2half2_rn(v1.z, v1.w);
    ((uint4*)d)[i] = *(uint4*)h;
}

// combine + end-of-launch re-zero of g_counts / g_flag (replay invariant)
__global__ __launch_bounds__(256) void combine_kernel(float* __restrict__ out) {
    int idx = blockIdx.x * blockDim.x + threadIdx.x;   // over N*H/4
    if (blockIdx.x == 0) {
        if (threadIdx.x < Edim) g_counts[threadIdx.x] = 0;
        g_flag[threadIdx.x] = 0;
    }
    int n = idx / (Hdim / 4);
    int c = idx % (Hdim / 4);
    float w0 = g_w[2*n],   w1 = g_w[2*n+1];
    int   p0 = g_pos[2*n], p1 = g_pos[2*n+1];
    __half2 a0 = ((const __half2*)(g_ogh + (size_t)p0 * Hdim))[2*c];
    __half2 a1 = ((const __half2*)(g_ogh + (size_t)p0 * Hdim))[2*c+1];
    __half2 b0 = ((const __half2*)(g_ogh + (size_t)p1 * Hdim))[2*c];
    __half2 b1 = ((const __half2*)(g_ogh + (size_t)p1 * Hdim))[2*c+1];
    float2 fa0 = __half22float2(a0), fa1 = __half22float2(a1);
    float2 fb0 = __half22float2(b0), fb1 = __half22float2(b1);
    float4 r;
    r.x = w0 * fa0.x + w1 * fb0.x;
    r.y = w0 * fa0.y + w1 * fb0.y;
    r.z = w0 * fa1.x + w1 * fb1.x;
    r.w = w0 * fa1.y + w1 * fb1.y;
    ((float4*)out)[idx] = r;
}

// ---------------- fused persistent grouped GEMM (GEMM1 + GEMM2) --------------
// One persistent launch walks the concatenated worklist tiles1 ++ tiles2.
// GEMM1 tiles (li < NT1): A = xtok[g_inv], K=1024, N=2048, silu -> hidh;
// after the epilogue each publishes flag[gmb] (threadfence + atomicAdd).
// GEMM2 tiles: A = hidh (pos order), K=2048, N=1024, plain -> ogh; before a
// GEMM2 tile's data can be prefetched, the CTA spins until flag[gmb] == 8.
// Deadlock-free: each CTA processes its (lower-index) tiles1 entries before
// reaching any tiles2 entry. A-loads use cp.async.cg (L2 path, no stale L1).
// Mainloop = the proven R14 pipeline (4-stage, wait_group 2, frag dbl-buffer).
#define STAGE_BYTES 49152
#define NSTAGE 4
#define SMEM_TOTAL (NSTAGE * STAGE_BYTES)

__global__ __launch_bounds__(256, 1) void moe_gemm_fused(
    const __half* __restrict__ xtok, const __half* __restrict__ w1h,
    __half* __restrict__ hidh, const __half* __restrict__ w2h,
    __half* __restrict__ ogh)
{
    int NT1 = g_nt[0];
    int NTT = NT1 + g_nt[1];
    int li  = blockIdx.x;
    if (li >= NTT) return;

    extern __shared__ char smem[];
    uint32_t sb = smem_u32(smem);
    int tid = threadIdx.x, wid = tid >> 5, lane = tid & 31;

    uint32_t d1 = sb + (uint32_t)tid * 128u;
    uint32_t x1 = (uint32_t)(tid & 7);
    uint32_t d2 = sb + (uint32_t)(tid + 256) * 128u;
    uint32_t x2 = (uint32_t)((tid + 256) & 7);
    bool two = tid < 128;

    int mw = wid & 1, nw = wid >> 1;
    int mA0 = mw * 64, nB0 = nw * 64;
    int rA = mA0 + ((lane >> 3) & 1) * 8 + (lane & 7);
    uint32_t jhA = (uint32_t)(lane >> 4);
    uint32_t xA  = (uint32_t)(rA & 7);
    uint32_t baseA[4];
    #pragma unroll
    for (int mt = 0; mt < 4; mt++) baseA[mt] = sb + (uint32_t)(rA + mt * 16) * 128u;
    uint32_t jhB = (uint32_t)((lane >> 3) & 1);
    uint32_t baseB[4], xB[4];
    #pragma unroll
    for (int p = 0; p < 4; p++) {
        int rB = nB0 + p * 16 + (lane >> 4) * 8 + (lane & 7);
        baseB[p] = sb + 16384u + (uint32_t)rB * 128u;
        xB[p]    = (uint32_t)(rB & 7);
    }

    // ---- decode current tile (always a GEMM1 tile at kernel start) ----------
    bool isG2 = false;
    int  Me, off, m0, n0, Nc, niter;
    const __half *gs1, *gs2;
    {
        int tn = g_tiles1[li];
        int e = tn >> 13, mb = (tn >> 5) & 0xFF, nb = tn & 31;
        Me = g_counts[e]; off = g_off[e];
        m0 = mb * 128; n0 = nb * 256;
        Nc = Idim; niter = Hdim >> 6;
        if (two) {
            int ridx = off + min(m0 + tid, NSLOT - 1 - off);
            gs1 = xtok + (size_t)g_inv[ridx] * Hdim;
        } else {
            gs1 = w1h + (size_t)e * Idim * Hdim + (size_t)(n0 + tid - 128) * Hdim;
        }
        gs2 = w1h + (size_t)e * Idim * Hdim + (size_t)(n0 + (tid & 127) + 128) * Hdim;
    }

    // ---- prologue: chunks 0..2 of current tile ------------------------------
    #pragma unroll
    for (int s = 0; s < NSTAGE - 1; s++) {
        uint32_t so = (uint32_t)s * STAGE_BYTES;
        const __half* g1 = gs1 + s * 64;
        #pragma unroll
        for (int j = 0; j < 8; j++) cp16(d1 + so + (((uint32_t)j ^ x1) << 4), g1 + j * 8);
        if (two) {
            const __half* g2 = gs2 + s * 64;
            #pragma unroll
            for (int j = 0; j < 8; j++) cp16(d2 + so + (((uint32_t)j ^ x2) << 4), g2 + j * 8);
        }
        asm volatile("cp.async.commit_group;");
    }

    float acc[4][8][4];
    uint32_t afr[2][16], bfr[2][16];

    while (true) {
        #pragma unroll
        for (int i = 0; i < 4; i++)
            #pragma unroll
            for (int j = 0; j < 8; j++)
                #pragma unroll
                for (int q = 0; q < 4; q++) acc[i][j][q] = 0.f;

        // ---- decode next tile; if GEMM2, wait for its GEMM1 deps ------------
        int li_n = li + gridDim.x;
        bool hn = li_n < NTT;
        bool isG2n = false;
        int Men = 0, offn = 0, m0n = 0, n0n = 0, Ncn = 0, nitern = 0;
        const __half *gs1n = nullptr, *gs2n = nullptr;
        if (hn) {
            isG2n = li_n >= NT1;
            int tn = isG2n ? g_tiles2[li_n - NT1] : g_tiles1[li_n];
            int e = tn >> 13, mb = (tn >> 5) & 0xFF, nb = tn & 31;
            Men = g_counts[e]; offn = g_off[e];
            m0n = mb * 128; n0n = nb * 256;
            int Kd = isG2n ? Idim : Hdim;
            Ncn = isG2n ? Hdim : Idim;
            nitern = Kd >> 6;
            const __half* Wb = isG2n ? w2h : w1h;
            if (two) {
                int ridx = offn + min(m0n + tid, NSLOT - 1 - offn);
                gs1n = isG2n ? (hidh + (size_t)ridx * Idim)
                             : (xtok + (size_t)g_inv[ridx] * Hdim);
            } else {
                gs1n = Wb + (size_t)e * Ncn * Kd + (size_t)(n0n + tid - 128) * Kd;
            }
            gs2n = Wb + (size_t)e * Ncn * Kd + (size_t)(n0n + (tid & 127) + 128) * Kd;

            if (isG2n) {
                int gmbn = (li_n - NT1) >> 2;
                if (tid == 0) {
                    while (atomicAdd(&g_flag[gmbn], 0) < 8) {}
                }
                __syncthreads();
                __threadfence();
            }
        }

        // ---- mainloop -------------------------------------------------------
        for (int it = 0; it < niter; ++it) {
            asm volatile("cp.async.wait_group 2;");
            __syncthreads();

            uint32_t soff = (uint32_t)(it & (NSTAGE - 1)) * STAGE_BYTES;

            // load ks = 0 into buf 0
            #pragma unroll
            for (int mt = 0; mt < 4; mt++) {
                uint32_t ad = baseA[mt] + soff + (((0u + jhA) ^ xA) << 4);
                ldsm_x4(ad, afr[0][4*mt+0], afr[0][4*mt+1], afr[0][4*mt+2], afr[0][4*mt+3]);
            }
            #pragma unroll
            for (int p = 0; p < 4; p++) {
                uint32_t bd = baseB[p] + soff + (((0u + jhB) ^ xB[p]) << 4);
                ldsm_x4(bd, bfr[0][4*p+0], bfr[0][4*p+1], bfr[0][4*p+2], bfr[0][4*p+3]);
            }

            #pragma unroll
            for (int ks = 0; ks < 4; ks++) {
                int cur = ks & 1, nxt = cur ^ 1;
                if (ks < 3) {   // prefetch ks+1 fragments before ks MMAs
                    uint32_t ko = (uint32_t)((ks + 1) << 1);
                    #pragma unroll
                    for (int mt = 0; mt < 4; mt++) {
                        uint32_t ad = baseA[mt] + soff + (((ko + jhA) ^ xA) << 4);
                        ldsm_x4(ad, afr[nxt][4*mt+0], afr[nxt][4*mt+1],
                                    afr[nxt][4*mt+2], afr[nxt][4*mt+3]);
                    }
                    #pragma unroll
                    for (int p = 0; p < 4; p++) {
                        uint32_t bd = baseB[p] + soff + (((ko + jhB) ^ xB[p]) << 4);
                        ldsm_x4(bd, bfr[nxt][4*p+0], bfr[nxt][4*p+1],
                                    bfr[nxt][4*p+2], bfr[nxt][4*p+3]);
                    }
                }
                #pragma unroll
                for (int p = 0; p < 4; p++) {
                    #pragma unroll
                    for (int mt = 0; mt < 4; mt++) {
                        mma_f16(acc[mt][2*p+0], &afr[cur][4*mt], bfr[cur][4*p+0], bfr[cur][4*p+1]);
                        mma_f16(acc[mt][2*p+1], &afr[cur][4*mt], bfr[cur][4*p+2], bfr[cur][4*p+3]);
                    }
                }
            }

            int nx = it + NSTAGE - 1;
            uint32_t so = (uint32_t)(nx & (NSTAGE - 1)) * STAGE_BYTES;
            if (nx < niter) {
                const __half* g1 = gs1 + nx * 64;
                #pragma unroll
                for (int j = 0; j < 8; j++) cp16(d1 + so + (((uint32_t)j ^ x1) << 4), g1 + j * 8);
                if (two) {
                    const __half* g2 = gs2 + nx * 64;
                    #pragma unroll
                    for (int j = 0; j < 8; j++) cp16(d2 + so + (((uint32_t)j ^ x2) << 4), g2 + j * 8);
                }
            } else if (hn) {
                int j0 = nx - niter;   // 0..2
                const __half* g1 = gs1n + j0 * 64;
                #pragma unroll
                for (int j = 0; j < 8; j++) cp16(d1 + so + (((uint32_t)j ^ x1) << 4), g1 + j * 8);
                if (two) {
                    const __half* g2 = gs2n + j0 * 64;
                    #pragma unroll
                    for (int j = 0; j < 8; j++) cp16(d2 + so + (((uint32_t)j ^ x2) << 4), g2 + j * 8);
                }
            }
            asm volatile("cp.async.commit_group;");
        }

        // ---- epilogue -------------------------------------------------------
        {
            __half* C = (isG2 ? ogh : hidh) + (size_t)off * Nc;
            #pragma unroll
            for (int mt = 0; mt < 4; mt++) {
                int ml0 = mA0 + mt * 16 + (lane >> 2);
                int ml1 = ml0 + 8;
                bool w0 = (m0 + ml0) < Me;
                bool w1 = (m0 + ml1) < Me;
                __half* c0 = C + (size_t)(m0 + ml0) * Nc + n0;
                __half* c1 = C + (size_t)(m0 + ml1) * Nc + n0;
                #pragma unroll
                for (int nt = 0; nt < 8; nt++) {
                    int col = nB0 + nt * 8 + (lane & 3) * 2;
                    float v0 = acc[mt][nt][0], v1 = acc[mt][nt][1];
                    float v2 = acc[mt][nt][2], v3 = acc[mt][nt][3];
                    if (!isG2) {
                        v0 = v0 / (1.f + __expf(-v0));
                        v1 = v1 / (1.f + __expf(-v1));
                        v2 = v2 / (1.f + __expf(-v2));
                        v3 = v3 / (1.f + __expf(-v3));
                    }
                    if (w0) *(__half2*)(c0 + col) = __floats2half2_rn(v0, v1);
                    if (w1) *(__half2*)(c1 + col) = __floats2half2_rn(v2, v3);
                }
            }
        }
        if (!isG2) {   // publish GEMM1 tile completion
            __threadfence();
            __syncthreads();
            if (tid == 0) atomicAdd(&g_flag[li >> 3], 1);
        }

        if (!hn) break;
        li = li_n; isG2 = isG2n;
        Me = Men; off = offn; m0 = m0n; n0 = n0n;
        Nc = Ncn; niter = nitern;
        gs1 = gs1n; gs2 = gs2n;
    }
}

// ---------------- launch ------------------------------------------------------
extern "C" void kernel_launch(void* const* d_in, const int* in_sizes, int n_in,
                              void* d_out, int out_size) {
    const float* x  = (const float*)d_in[0];
    const float* Wg = (const float*)d_in[1];
    const float* W1 = (const float*)d_in[2];
    const float* W2 = (const float*)d_in[3];
    float* out = (float*)d_out;

    __half *xtok = nullptr, *hidh = nullptr, *ogh = nullptr, *w1h = nullptr, *w2h = nullptr;
    cudaGetSymbolAddress((void**)&xtok, g_xtok);
    cudaGetSymbolAddress((void**)&hidh, g_hidh);
    cudaGetSymbolAddress((void**)&ogh,  g_ogh);
    cudaGetSymbolAddress((void**)&w1h,  g_w1h);
    cudaGetSymbolAddress((void**)&w2h,  g_w2h);

    static int nsm = 0;
    static cudaStream_t s2;
    static cudaEvent_t ev_fork, ev_w2;
    if (nsm == 0) {
        cudaFuncSetAttribute(moe_gemm_fused, cudaFuncAttributeMaxDynamicSharedMemorySize,
                             SMEM_TOTAL);
        cudaDeviceGetAttribute(&nsm, cudaDevAttrMultiProcessorCount, 0);
        if (nsm <= 0) nsm = 148;
        cudaStreamCreateWithFlags(&s2, cudaStreamNonBlocking);
        cudaEventCreateWithFlags(&ev_fork, cudaEventDisableTiming);
        cudaEventCreateWithFlags(&ev_w2,   cudaEventDisableTiming);
    }

    // fork: x conversion + both weight conversions overlap gating
    cudaEventRecord(ev_fork, 0);
    cudaStreamWaitEvent(s2, ev_fork, 0);
    xconv_kernel<<<(Ntok * Hdim / 8) / 256, 256, 0, s2>>>(x, xtok);
    f2h_kernel<<<(W1ELEMS / 8 + 255) / 256, 256, 0, s2>>>(W1, w1h, W1ELEMS / 8);
    f2h_kernel<<<(W2ELEMS / 8 + 255) / 256, 256, 0, s2>>>(W2, w2h, W2ELEMS / 8);
    cudaEventRecord(ev_w2, s2);

    // main: gate (counts/flags start at 0 — zeroed by combine at end of the
    // previous launch/replay, and by static zero-init on the very first run)
    gate_kernel<<<Ntok, 256>>>(x, Wg);
    scan_build_kernel<<<1, 256>>>();
    pos_kernel<<<NSLOT / 256, 256>>>();

    cudaStreamWaitEvent(0, ev_w2, 0);
    // fused GEMM1 + GEMM2 (flag-pipelined persistent kernel)
    moe_gemm_fused<<<nsm, 256, SMEM_TOTAL>>>(xtok, w1h, hidh, w2h, ogh);

    combine_kernel<<<(Ntok * Hdim / 4) / 256, 256>>>(out);
}